// round 1
// baseline (speedup 1.0000x reference)
#include <cuda_runtime.h>

#define NN 50000
#define NE 600000
#define NT (NE + NN)
#define HID 128
#define NG 128
#define NC 5

// ---------------- device scratch (no allocs allowed) ----------------
__device__ int   g_cnt[NN];
__device__ float g_dis[NN];
__device__ int   g_rowptr[NN + 1];
__device__ int   g_col[NT];
__device__ float g_wn[NT];
__device__ float g_h[NN * HID];
__device__ float g_agg[NN * HID];
__device__ float g_pool[NG * HID];

// ---------------- graph normalization ----------------
__global__ void k_init() {
    int i = blockIdx.x * blockDim.x + threadIdx.x;
    if (i < NN) g_cnt[i] = 1;  // self loop
}

__global__ void k_deg(const int* __restrict__ dst) {
    int e = blockIdx.x * blockDim.x + threadIdx.x;
    if (e < NE) atomicAdd(&g_cnt[dst[e]], 1);
}

__global__ void k_dis() {
    int i = blockIdx.x * blockDim.x + threadIdx.x;
    if (i < NN) g_dis[i] = rsqrtf((float)g_cnt[i]);  // deg >= 1 always
}

// single-block exclusive scan of g_cnt -> g_rowptr, resets g_cnt to 0
__global__ void k_scan() {
    __shared__ int wsum[32];
    __shared__ int carry_s;
    int tid = threadIdx.x;
    int lane = tid & 31, wid = tid >> 5;
    if (tid == 0) carry_s = 0;
    __syncthreads();
    for (int base = 0; base < NN; base += 1024) {
        int i = base + tid;
        int v = (i < NN) ? g_cnt[i] : 0;
        int x = v;
        #pragma unroll
        for (int o = 1; o < 32; o <<= 1) {
            int y = __shfl_up_sync(0xffffffffu, x, o);
            if (lane >= o) x += y;
        }
        if (lane == 31) wsum[wid] = x;
        __syncthreads();
        if (wid == 0) {
            int w = wsum[lane];
            #pragma unroll
            for (int o = 1; o < 32; o <<= 1) {
                int y = __shfl_up_sync(0xffffffffu, w, o);
                if (lane >= o) w += y;
            }
            wsum[lane] = w;
        }
        __syncthreads();
        int incl = x + (wid > 0 ? wsum[wid - 1] : 0) + carry_s;
        if (i < NN) { g_rowptr[i] = incl - v; g_cnt[i] = 0; }
        __syncthreads();
        if (tid == 1023) carry_s = incl;
        __syncthreads();
    }
    if (tid == 0) g_rowptr[NN] = carry_s;
}

__global__ void k_fill(const int* __restrict__ src, const int* __restrict__ dst) {
    int t = blockIdx.x * blockDim.x + threadIdx.x;
    if (t >= NT) return;
    int s, d;
    if (t < NE) { s = src[t]; d = dst[t]; }
    else        { s = d = t - NE; }            // self loops
    int pos = atomicAdd(&g_cnt[d], 1);
    int o = g_rowptr[d] + pos;
    g_col[o] = s;
    g_wn[o]  = g_dis[s] * g_dis[d];
}

// ---------------- layer 1: h = relu((A x) W1 + b1)   (x is [N,3]) ----------------
__global__ void k_layer1(const float* __restrict__ x, const float* __restrict__ W1,
                         const float* __restrict__ b1) {
    int node = blockIdx.x * 8 + (threadIdx.x >> 5);
    if (node >= NN) return;
    int lane = threadIdx.x & 31;
    int beg = g_rowptr[node], end = g_rowptr[node + 1];
    float a0 = 0.f, a1 = 0.f, a2 = 0.f;
    for (int j = beg + lane; j < end; j += 32) {
        int s = g_col[j];
        float w = g_wn[j];
        a0 += w * x[s * 3 + 0];
        a1 += w * x[s * 3 + 1];
        a2 += w * x[s * 3 + 2];
    }
    #pragma unroll
    for (int o = 16; o; o >>= 1) {
        a0 += __shfl_down_sync(0xffffffffu, a0, o);
        a1 += __shfl_down_sync(0xffffffffu, a1, o);
        a2 += __shfl_down_sync(0xffffffffu, a2, o);
    }
    a0 = __shfl_sync(0xffffffffu, a0, 0);
    a1 = __shfl_sync(0xffffffffu, a1, 0);
    a2 = __shfl_sync(0xffffffffu, a2, 0);
    #pragma unroll
    for (int k = 0; k < 4; k++) {
        int c = lane * 4 + k;
        float v = a0 * W1[c] + a1 * W1[128 + c] + a2 * W1[256 + c] + b1[c];
        g_h[(size_t)node * 128 + c] = fmaxf(v, 0.f);
    }
}

// ---------------- propagate: g_agg = A * g_h  (warp per node, lane = 4 channels) ----------------
__global__ void k_prop() {
    int node = blockIdx.x * 8 + (threadIdx.x >> 5);
    if (node >= NN) return;
    int lane = threadIdx.x & 31;
    int beg = g_rowptr[node], end = g_rowptr[node + 1];
    float4 acc = make_float4(0.f, 0.f, 0.f, 0.f);
    for (int j = beg; j < end; j++) {
        int s = g_col[j];
        float w = g_wn[j];
        float4 v = *(const float4*)(g_h + (size_t)s * 128 + lane * 4);
        acc.x += w * v.x; acc.y += w * v.y; acc.z += w * v.z; acc.w += w * v.w;
    }
    *(float4*)(g_agg + (size_t)node * 128 + lane * 4) = acc;
}

// ---------------- GEMM: g_h = relu(g_agg @ W + b)   [N,128]x[128,128] ----------------
__global__ __launch_bounds__(256) void k_gemm(const float* __restrict__ W,
                                              const float* __restrict__ bias) {
    __shared__ float sA[64][32];
    __shared__ float sB[32][128];
    int t = threadIdx.x;
    int tx = t & 31, ty = t >> 5;          // warp = ty, lane = tx
    int row0 = blockIdx.x * 64;
    float4 acc[8];
    #pragma unroll
    for (int i = 0; i < 8; i++) acc[i] = make_float4(0.f, 0.f, 0.f, 0.f);

    for (int k0 = 0; k0 < 128; k0 += 32) {
        #pragma unroll
        for (int i = 0; i < 2; i++) {      // A tile: 64x32 = 512 float4
            int lin = t + i * 256;
            int r = lin >> 3, cq = lin & 7;
            float4 v = make_float4(0.f, 0.f, 0.f, 0.f);
            if (row0 + r < NN)
                v = *(const float4*)(g_agg + (size_t)(row0 + r) * 128 + k0 + cq * 4);
            *(float4*)&sA[r][cq * 4] = v;
        }
        #pragma unroll
        for (int i = 0; i < 4; i++) {      // B tile: 32x128 = 1024 float4
            int lin = t + i * 256;
            int kk = lin >> 5, q = lin & 31;
            *(float4*)&sB[kk][q * 4] = *(const float4*)(W + (size_t)(k0 + kk) * 128 + q * 4);
        }
        __syncthreads();
        #pragma unroll
        for (int kk = 0; kk < 32; kk++) {
            float4 bv = *(const float4*)&sB[kk][tx * 4];
            #pragma unroll
            for (int i = 0; i < 8; i++) {
                float a = sA[ty * 8 + i][kk];   // uniform within warp -> broadcast
                acc[i].x += a * bv.x; acc[i].y += a * bv.y;
                acc[i].z += a * bv.z; acc[i].w += a * bv.w;
            }
        }
        __syncthreads();
    }
    float4 bv = *(const float4*)(bias + tx * 4);
    #pragma unroll
    for (int i = 0; i < 8; i++) {
        int r = row0 + ty * 8 + i;
        if (r < NN) {
            float4 o;
            o.x = fmaxf(acc[i].x + bv.x, 0.f);
            o.y = fmaxf(acc[i].y + bv.y, 0.f);
            o.z = fmaxf(acc[i].z + bv.z, 0.f);
            o.w = fmaxf(acc[i].w + bv.w, 0.f);
            *(float4*)(g_h + (size_t)r * 128 + tx * 4) = o;
        }
    }
}

// ---------------- mean pool per graph (batch is sorted -> binary search bounds) ----------------
__global__ void k_pool(const int* __restrict__ batch) {
    int g = blockIdx.x;   // 0..127
    int c = threadIdx.x;  // 0..127
    int lo = 0, hi = NN;
    while (lo < hi) { int m = (lo + hi) >> 1; if (batch[m] < g) lo = m + 1; else hi = m; }
    int st = lo;
    lo = st; hi = NN;
    while (lo < hi) { int m = (lo + hi) >> 1; if (batch[m] < g + 1) lo = m + 1; else hi = m; }
    int en = lo;
    float s = 0.f;
    for (int n = st; n < en; n++) s += g_h[(size_t)n * 128 + c];
    int cnt = en - st;
    g_pool[g * 128 + c] = s / (float)(cnt > 0 ? cnt : 1);
}

// ---------------- final linear: out = pool @ Wl + bl  [128,5] ----------------
__global__ void k_final(const float* __restrict__ Wl, const float* __restrict__ bl,
                        float* __restrict__ out) {
    int t = blockIdx.x * blockDim.x + threadIdx.x;
    if (t >= NG * NC) return;
    int g = t / NC, c = t % NC;
    float s = bl[c];
    #pragma unroll 8
    for (int k = 0; k < 128; k++) s += g_pool[g * 128 + k] * Wl[k * 5 + c];
    out[t] = s;
}

extern "C" void kernel_launch(void* const* d_in, const int* in_sizes, int n_in,
                              void* d_out, int out_size) {
    const float* x     = (const float*)d_in[0];
    const int*   ei    = (const int*)d_in[1];
    const int*   batch = (const int*)d_in[2];
    const float* W1    = (const float*)d_in[3];
    const float* b1    = (const float*)d_in[4];
    const float* W2    = (const float*)d_in[5];
    const float* b2    = (const float*)d_in[6];
    const float* W3    = (const float*)d_in[7];
    const float* b3    = (const float*)d_in[8];
    const float* Wl    = (const float*)d_in[9];
    const float* bl    = (const float*)d_in[10];
    float* out = (float*)d_out;

    const int* src = ei;          // edge_index[0]
    const int* dst = ei + NE;     // edge_index[1]

    // graph norm + CSR build
    k_init<<<(NN + 255) / 256, 256>>>();
    k_deg <<<(NE + 255) / 256, 256>>>(dst);
    k_dis <<<(NN + 255) / 256, 256>>>();
    k_scan<<<1, 1024>>>();
    k_fill<<<(NT + 255) / 256, 256>>>(src, dst);

    // layer 1 (fused propagate-3dim + small GEMM + bias + relu)
    k_layer1<<<(NN + 7) / 8, 256>>>(x, W1, b1);

    // layer 2
    k_prop<<<(NN + 7) / 8, 256>>>();
    k_gemm<<<(NN + 63) / 64, 256>>>(W2, b2);

    // layer 3
    k_prop<<<(NN + 7) / 8, 256>>>();
    k_gemm<<<(NN + 63) / 64, 256>>>(W3, b3);

    // pool + classifier head
    k_pool<<<NG, HID>>>(batch);
    k_final<<<(NG * NC + 127) / 128, 128>>>(Wl, bl, out);
}

// round 6
// speedup vs baseline: 1.0028x; 1.0028x over previous
#include <cuda_runtime.h>

#define NN 50000
#define NE 600000
#define NT (NE + NN)
#define HID 128
#define NG 128
#define NC 5
#define NBLK ((NN + 255) / 256)   // 196

// ---------------- device scratch (no allocs allowed) ----------------
__device__ int   g_cnt[NN];
__device__ float g_dis[NN];
__device__ int   g_rowptr[NN + 1];
__device__ int   g_bsum[256];
__device__ int   g_boff[256];
__device__ int   g_col[NT];
__device__ float g_wn[NT];
__device__ float g_h[NN * HID];
__device__ float g_agg[NN * HID];
__device__ float g_pool[NG * HID];

// packed fp32x2 FMA (SASS FFMA2 — double-rate fp32, only reachable via PTX)
#define FFMA2(d, a, b) asm("fma.rn.f32x2 %0, %1, %2, %0;" : "+l"(d) : "l"(a), "l"(b))

// ---------------- graph normalization ----------------
__global__ void k_init() {
    int i = blockIdx.x * blockDim.x + threadIdx.x;
    if (i < NN) g_cnt[i] = 1;  // self loop
}

__global__ void k_deg(const int* __restrict__ dst) {
    int e = blockIdx.x * blockDim.x + threadIdx.x;
    if (e < NE) atomicAdd(&g_cnt[dst[e]], 1);
}

__device__ __forceinline__ int block_excl_scan_256(int v, int tid, int* wsum) {
    int lane = tid & 31, wid = tid >> 5;
    int x = v;
    #pragma unroll
    for (int o = 1; o < 32; o <<= 1) {
        int y = __shfl_up_sync(0xffffffffu, x, o);
        if (lane >= o) x += y;
    }
    if (lane == 31) wsum[wid] = x;
    __syncthreads();
    if (wid == 0) {
        int w = (lane < 8) ? wsum[lane] : 0;
        #pragma unroll
        for (int o = 1; o < 8; o <<= 1) {
            int y = __shfl_up_sync(0xffffffffu, w, o);
            if (lane >= o) w += y;
        }
        if (lane < 8) wsum[lane] = w;
    }
    __syncthreads();
    return x - v + (wid ? wsum[wid - 1] : 0);
}

// phase A: per-block exclusive scan of degrees; also compute dis, reset cnt
__global__ void k_scanA() {
    __shared__ int wsum[8];
    int tid = threadIdx.x;
    int i = blockIdx.x * 256 + tid;
    int v = 0;
    if (i < NN) {
        v = g_cnt[i];
        g_dis[i] = rsqrtf((float)v);   // deg >= 1 always
        g_cnt[i] = 0;                  // reused as cursor by k_fill
    }
    int excl = block_excl_scan_256(v, tid, wsum);
    if (i < NN) g_rowptr[i] = excl;
    if (tid == 255) g_bsum[blockIdx.x] = excl + v;
}

// phase B: scan the 196 block sums (single block)
__global__ void k_scanB() {
    __shared__ int wsum[8];
    int tid = threadIdx.x;
    int v = (tid < NBLK) ? g_bsum[tid] : 0;
    int excl = block_excl_scan_256(v, tid, wsum);
    if (tid < NBLK) g_boff[tid] = excl;
}

// phase C: add block offsets
__global__ void k_scanC() {
    int i = blockIdx.x * blockDim.x + threadIdx.x;
    if (i < NN) g_rowptr[i] += g_boff[i >> 8];
    if (i == 0) g_rowptr[NN] = NT;     // total is known
}

__global__ void k_fill(const int* __restrict__ src, const int* __restrict__ dst) {
    int t = blockIdx.x * blockDim.x + threadIdx.x;
    if (t >= NT) return;
    int s, d;
    if (t < NE) { s = src[t]; d = dst[t]; }
    else        { s = d = t - NE; }            // self loops
    int pos = atomicAdd(&g_cnt[d], 1);
    int o = g_rowptr[d] + pos;
    g_col[o] = s;
    g_wn[o]  = g_dis[s] * g_dis[d];
}

// ---------------- layer 1: h = relu((A x) W1 + b1)   (x is [N,3]) ----------------
__global__ void k_layer1(const float* __restrict__ x, const float* __restrict__ W1,
                         const float* __restrict__ b1) {
    int node = blockIdx.x * 8 + (threadIdx.x >> 5);
    if (node >= NN) return;
    int lane = threadIdx.x & 31;
    int beg = g_rowptr[node], end = g_rowptr[node + 1];
    float a0 = 0.f, a1 = 0.f, a2 = 0.f;
    for (int j = beg + lane; j < end; j += 32) {
        int s = g_col[j];
        float w = g_wn[j];
        a0 += w * x[s * 3 + 0];
        a1 += w * x[s * 3 + 1];
        a2 += w * x[s * 3 + 2];
    }
    #pragma unroll
    for (int o = 16; o; o >>= 1) {
        a0 += __shfl_down_sync(0xffffffffu, a0, o);
        a1 += __shfl_down_sync(0xffffffffu, a1, o);
        a2 += __shfl_down_sync(0xffffffffu, a2, o);
    }
    a0 = __shfl_sync(0xffffffffu, a0, 0);
    a1 = __shfl_sync(0xffffffffu, a1, 0);
    a2 = __shfl_sync(0xffffffffu, a2, 0);
    #pragma unroll
    for (int k = 0; k < 4; k++) {
        int c = lane * 4 + k;
        float v = a0 * W1[c] + a1 * W1[128 + c] + a2 * W1[256 + c] + b1[c];
        g_h[(size_t)node * 128 + c] = fmaxf(v, 0.f);
    }
}

// ---------------- propagate: g_agg = A * g_h (warp/node, lane = 4 channels) ----------------
__global__ void k_prop() {
    int node = blockIdx.x * 8 + (threadIdx.x >> 5);
    if (node >= NN) return;
    int lane = threadIdx.x & 31;
    int beg = g_rowptr[node], end = g_rowptr[node + 1];
    float4 acc  = make_float4(0.f, 0.f, 0.f, 0.f);
    float4 acc2 = make_float4(0.f, 0.f, 0.f, 0.f);
    int j = beg;
    for (; j + 1 < end; j += 2) {
        int s0 = g_col[j], s1 = g_col[j + 1];
        float w0 = g_wn[j], w1 = g_wn[j + 1];
        float4 v0 = *(const float4*)(g_h + (size_t)s0 * 128 + lane * 4);
        float4 v1 = *(const float4*)(g_h + (size_t)s1 * 128 + lane * 4);
        acc.x  += w0 * v0.x; acc.y  += w0 * v0.y; acc.z  += w0 * v0.z; acc.w  += w0 * v0.w;
        acc2.x += w1 * v1.x; acc2.y += w1 * v1.y; acc2.z += w1 * v1.z; acc2.w += w1 * v1.w;
    }
    if (j < end) {
        int s = g_col[j];
        float w = g_wn[j];
        float4 v = *(const float4*)(g_h + (size_t)s * 128 + lane * 4);
        acc.x += w * v.x; acc.y += w * v.y; acc.z += w * v.z; acc.w += w * v.w;
    }
    acc.x += acc2.x; acc.y += acc2.y; acc.z += acc2.z; acc.w += acc2.w;
    *(float4*)(g_agg + (size_t)node * 128 + lane * 4) = acc;
}

// ---------------- GEMM: g_h = relu(g_agg @ W + b)  [N,128]x[128,128], f32x2 ----------------
#define BM 128
#define BK 16
#define PITCHA (2 * BM + 4)   // duplicated A row pitch (floats), 16B-aligned rows

__global__ __launch_bounds__(256, 2) void k_gemm(const float* __restrict__ W,
                                                 const float* __restrict__ bias) {
    __shared__ float sA[BK][PITCHA];   // sA[k][2m], value duplicated at 2m and 2m+1
    __shared__ float sB[BK][HID];
    int t = threadIdx.x;
    int tx = t & 15, ty = t >> 4;
    int row0 = blockIdx.x * BM;

    unsigned long long acc[8][4];
    #pragma unroll
    for (int m = 0; m < 8; m++)
        #pragma unroll
        for (int n = 0; n < 4; n++) acc[m][n] = 0ull;

    for (int k0 = 0; k0 < HID; k0 += BK) {
        // A tile: 128 rows x 16 cols = 512 float4; store duplicated
        #pragma unroll
        for (int i = 0; i < 2; i++) {
            int lin = t + i * 256;       // 0..511
            int r = lin >> 2;            // 0..127
            int cq = lin & 3;            // 0..3
            float4 v = make_float4(0.f, 0.f, 0.f, 0.f);
            if (row0 + r < NN)
                v = *(const float4*)(g_agg + (size_t)(row0 + r) * 128 + k0 + cq * 4);
            float vv[4] = {v.x, v.y, v.z, v.w};
            #pragma unroll
            for (int cc = 0; cc < 4; cc++) {
                float2 d2 = make_float2(vv[cc], vv[cc]);
                *(float2*)&sA[cq * 4 + cc][2 * r] = d2;
            }
        }
        // B tile: 16 x 128 = 512 float4
        #pragma unroll
        for (int i = 0; i < 2; i++) {
            int lin = t + i * 256;
            int kk = lin >> 5, q = lin & 31;
            *(float4*)&sB[kk][q * 4] = *(const float4*)(W + (size_t)(k0 + kk) * 128 + q * 4);
        }
        __syncthreads();
        #pragma unroll
        for (int kk = 0; kk < BK; kk++) {
            ulonglong2 a01 = *(const ulonglong2*)&sA[kk][ty * 16 + 0];
            ulonglong2 a23 = *(const ulonglong2*)&sA[kk][ty * 16 + 4];
            ulonglong2 a45 = *(const ulonglong2*)&sA[kk][ty * 16 + 8];
            ulonglong2 a67 = *(const ulonglong2*)&sA[kk][ty * 16 + 12];
            ulonglong2 b01 = *(const ulonglong2*)&sB[kk][tx * 8 + 0];
            ulonglong2 b23 = *(const ulonglong2*)&sB[kk][tx * 8 + 4];
            unsigned long long av[8] = {a01.x, a01.y, a23.x, a23.y,
                                        a45.x, a45.y, a67.x, a67.y};
            unsigned long long bv[4] = {b01.x, b01.y, b23.x, b23.y};
            #pragma unroll
            for (int m = 0; m < 8; m++) {
                FFMA2(acc[m][0], av[m], bv[0]);
                FFMA2(acc[m][1], av[m], bv[1]);
                FFMA2(acc[m][2], av[m], bv[2]);
                FFMA2(acc[m][3], av[m], bv[3]);
            }
        }
        __syncthreads();
    }
    // epilogue: bias + relu
    float4 bv0 = *(const float4*)(bias + tx * 8 + 0);
    float4 bv1 = *(const float4*)(bias + tx * 8 + 4);
    float bb[8] = {bv0.x, bv0.y, bv0.z, bv0.w, bv1.x, bv1.y, bv1.z, bv1.w};
    #pragma unroll
    for (int m = 0; m < 8; m++) {
        int r = row0 + ty * 8 + m;
        if (r < NN) {
            float o[8];
            #pragma unroll
            for (int n = 0; n < 4; n++) {
                float2 p = *(float2*)&acc[m][n];
                o[2 * n]     = fmaxf(p.x + bb[2 * n], 0.f);
                o[2 * n + 1] = fmaxf(p.y + bb[2 * n + 1], 0.f);
            }
            *(float4*)(g_h + (size_t)r * 128 + tx * 8 + 0) = make_float4(o[0], o[1], o[2], o[3]);
            *(float4*)(g_h + (size_t)r * 128 + tx * 8 + 4) = make_float4(o[4], o[5], o[6], o[7]);
        }
    }
}

// ---------------- mean pool per graph (batch sorted -> binary search bounds) ----------------
__global__ void k_pool(const int* __restrict__ batch) {
    int g = blockIdx.x;   // 0..127
    int c = threadIdx.x;  // 0..127
    int lo = 0, hi = NN;
    while (lo < hi) { int m = (lo + hi) >> 1; if (batch[m] < g) lo = m + 1; else hi = m; }
    int st = lo;
    lo = st; hi = NN;
    while (lo < hi) { int m = (lo + hi) >> 1; if (batch[m] < g + 1) lo = m + 1; else hi = m; }
    int en = lo;
    float s0 = 0.f, s1 = 0.f, s2 = 0.f, s3 = 0.f;
    int n = st;
    for (; n + 3 < en; n += 4) {
        s0 += g_h[(size_t)(n + 0) * 128 + c];
        s1 += g_h[(size_t)(n + 1) * 128 + c];
        s2 += g_h[(size_t)(n + 2) * 128 + c];
        s3 += g_h[(size_t)(n + 3) * 128 + c];
    }
    for (; n < en; n++) s0 += g_h[(size_t)n * 128 + c];
    float s = (s0 + s1) + (s2 + s3);
    int cnt = en - st;
    g_pool[g * 128 + c] = s / (float)(cnt > 0 ? cnt : 1);
}

// ---------------- final linear: out = pool @ Wl + bl  [128,5] ----------------
__global__ void k_final(const float* __restrict__ Wl, const float* __restrict__ bl,
                        float* __restrict__ out) {
    int t = blockIdx.x * blockDim.x + threadIdx.x;
    if (t >= NG * NC) return;
    int g = t / NC, c = t % NC;
    float s = bl[c];
    #pragma unroll 8
    for (int k = 0; k < 128; k++) s += g_pool[g * 128 + k] * Wl[k * 5 + c];
    out[t] = s;
}

extern "C" void kernel_launch(void* const* d_in, const int* in_sizes, int n_in,
                              void* d_out, int out_size) {
    const float* x     = (const float*)d_in[0];
    const int*   ei    = (const int*)d_in[1];
    const int*   batch = (const int*)d_in[2];
    const float* W1    = (const float*)d_in[3];
    const float* b1    = (const float*)d_in[4];
    const float* W2    = (const float*)d_in[5];
    const float* b2    = (const float*)d_in[6];
    const float* W3    = (const float*)d_in[7];
    const float* b3    = (const float*)d_in[8];
    const float* Wl    = (const float*)d_in[9];
    const float* bl    = (const float*)d_in[10];
    float* out = (float*)d_out;

    const int* src = ei;          // edge_index[0]
    const int* dst = ei + NE;     // edge_index[1]

    // graph norm + CSR build (parallel scan)
    k_init <<<(NN + 255) / 256, 256>>>();
    k_deg  <<<(NE + 255) / 256, 256>>>(dst);
    k_scanA<<<NBLK, 256>>>();
    k_scanB<<<1, 256>>>();
    k_scanC<<<NBLK, 256>>>();
    k_fill <<<(NT + 255) / 256, 256>>>(src, dst);

    // layer 1 (fused propagate-3dim + tiny GEMM + bias + relu)
    k_layer1<<<(NN + 7) / 8, 256>>>(x, W1, b1);

    // layer 2
    k_prop<<<(NN + 7) / 8, 256>>>();
    k_gemm<<<(NN + 127) / 128, 256>>>(W2, b2);

    // layer 3
    k_prop<<<(NN + 7) / 8, 256>>>();
    k_gemm<<<(NN + 127) / 128, 256>>>(W3, b3);

    // pool + classifier head
    k_pool<<<NG, HID>>>(batch);
    k_final<<<(NG * NC + 127) / 128, 128>>>(Wl, bl, out);
}

// round 8
// speedup vs baseline: 1.6962x; 1.6916x over previous
#include <cuda_runtime.h>
#include <cuda_fp16.h>

#define NN 50000
#define NE 600000
#define NT (NE + NN)
#define HID 128
#define NG 128
#define NC 5
#define NBLK ((NN + 255) / 256)   // 196

// bit-cast helpers (the __half2<->uint intrinsics don't exist)
__device__ __forceinline__ unsigned h2_as_u(__half2 h) {
    return *reinterpret_cast<unsigned*>(&h);
}
__device__ __forceinline__ __half2 u_as_h2(unsigned u) {
    return *reinterpret_cast<__half2*>(&u);
}

// ---------------- device scratch (no allocs allowed) ----------------
__device__ int   g_cnt[NN];
__device__ float g_dis[NN];
__device__ int   g_rowptr[NN + 1];
__device__ int   g_bsum[256];
__device__ int   g_boff[256];
__device__ uint2 g_ew[NT];                       // packed {col, w_bits}
__device__ __align__(16) __half g_hh[NN * HID];  // activations (fp16)
__device__ __align__(16) __half g_ah[NN * HID];  // aggregated (fp16)
__device__ float g_pool[NG * HID];

// ---------------- graph normalization ----------------
__global__ void k_init() {
    int i = blockIdx.x * blockDim.x + threadIdx.x;
    if (i < NN) g_cnt[i] = 1;  // self loop
}

__global__ void k_deg(const int* __restrict__ dst) {
    int e = blockIdx.x * blockDim.x + threadIdx.x;
    if (e < NE) atomicAdd(&g_cnt[dst[e]], 1);
}

__device__ __forceinline__ int block_excl_scan_256(int v, int tid, int* wsum) {
    int lane = tid & 31, wid = tid >> 5;
    int x = v;
    #pragma unroll
    for (int o = 1; o < 32; o <<= 1) {
        int y = __shfl_up_sync(0xffffffffu, x, o);
        if (lane >= o) x += y;
    }
    if (lane == 31) wsum[wid] = x;
    __syncthreads();
    if (wid == 0) {
        int w = (lane < 8) ? wsum[lane] : 0;
        #pragma unroll
        for (int o = 1; o < 8; o <<= 1) {
            int y = __shfl_up_sync(0xffffffffu, w, o);
            if (lane >= o) w += y;
        }
        if (lane < 8) wsum[lane] = w;
    }
    __syncthreads();
    return x - v + (wid ? wsum[wid - 1] : 0);
}

__global__ void k_scanA() {
    __shared__ int wsum[8];
    int tid = threadIdx.x;
    int i = blockIdx.x * 256 + tid;
    int v = 0;
    if (i < NN) {
        v = g_cnt[i];
        g_dis[i] = rsqrtf((float)v);
        g_cnt[i] = 0;                  // reused as cursor by k_fill
    }
    int excl = block_excl_scan_256(v, tid, wsum);
    if (i < NN) g_rowptr[i] = excl;
    if (tid == 255) g_bsum[blockIdx.x] = excl + v;
}

__global__ void k_scanB() {
    __shared__ int wsum[8];
    int tid = threadIdx.x;
    int v = (tid < NBLK) ? g_bsum[tid] : 0;
    int excl = block_excl_scan_256(v, tid, wsum);
    if (tid < NBLK) g_boff[tid] = excl;
}

__global__ void k_scanC() {
    int i = blockIdx.x * blockDim.x + threadIdx.x;
    if (i < NN) g_rowptr[i] += g_boff[i >> 8];
    if (i == 0) g_rowptr[NN] = NT;
}

__global__ void k_fill(const int* __restrict__ src, const int* __restrict__ dst) {
    int t = blockIdx.x * blockDim.x + threadIdx.x;
    if (t >= NT) return;
    int s, d;
    if (t < NE) { s = src[t]; d = dst[t]; }
    else        { s = d = t - NE; }            // self loops
    int pos = atomicAdd(&g_cnt[d], 1);
    int o = g_rowptr[d] + pos;
    uint2 v;
    v.x = (unsigned)s;
    v.y = __float_as_uint(g_dis[s] * g_dis[d]);
    g_ew[o] = v;
}

// ---------------- layer 1: h = relu((A x) W1 + b1)   (x is [N,3]) ----------------
__global__ void k_layer1(const float* __restrict__ x, const float* __restrict__ W1,
                         const float* __restrict__ b1) {
    int node = blockIdx.x * 8 + (threadIdx.x >> 5);
    if (node >= NN) return;
    int lane = threadIdx.x & 31;
    int beg = g_rowptr[node], end = g_rowptr[node + 1];
    float a0 = 0.f, a1 = 0.f, a2 = 0.f;
    for (int j = beg + lane; j < end; j += 32) {
        uint2 e = g_ew[j];
        int s = (int)e.x;
        float w = __uint_as_float(e.y);
        a0 += w * x[s * 3 + 0];
        a1 += w * x[s * 3 + 1];
        a2 += w * x[s * 3 + 2];
    }
    #pragma unroll
    for (int o = 16; o; o >>= 1) {
        a0 += __shfl_down_sync(0xffffffffu, a0, o);
        a1 += __shfl_down_sync(0xffffffffu, a1, o);
        a2 += __shfl_down_sync(0xffffffffu, a2, o);
    }
    a0 = __shfl_sync(0xffffffffu, a0, 0);
    a1 = __shfl_sync(0xffffffffu, a1, 0);
    a2 = __shfl_sync(0xffffffffu, a2, 0);
    int c = lane * 4;
    float v0 = fmaxf(a0 * W1[c+0] + a1 * W1[128+c+0] + a2 * W1[256+c+0] + b1[c+0], 0.f);
    float v1 = fmaxf(a0 * W1[c+1] + a1 * W1[128+c+1] + a2 * W1[256+c+1] + b1[c+1], 0.f);
    float v2 = fmaxf(a0 * W1[c+2] + a1 * W1[128+c+2] + a2 * W1[256+c+2] + b1[c+2], 0.f);
    float v3 = fmaxf(a0 * W1[c+3] + a1 * W1[128+c+3] + a2 * W1[256+c+3] + b1[c+3], 0.f);
    uint2 p;
    p.x = h2_as_u(__float22half2_rn(make_float2(v0, v1)));
    p.y = h2_as_u(__float22half2_rn(make_float2(v2, v3)));
    *(uint2*)(g_hh + (size_t)node * 128 + c) = p;
}

// ---------------- propagate: g_ah = A * g_hh  (warp/node, lane = 4 ch, fp16) ----------------
__global__ void k_prop() {
    int node = blockIdx.x * 8 + (threadIdx.x >> 5);
    if (node >= NN) return;
    int lane = threadIdx.x & 31;
    int beg = g_rowptr[node], end = g_rowptr[node + 1];
    float4 acc  = make_float4(0.f, 0.f, 0.f, 0.f);
    float4 acc2 = make_float4(0.f, 0.f, 0.f, 0.f);
    int j = beg;
    for (; j + 1 < end; j += 2) {
        uint2 e0 = g_ew[j], e1 = g_ew[j + 1];
        float w0 = __uint_as_float(e0.y), w1 = __uint_as_float(e1.y);
        uint2 h0 = *(const uint2*)(g_hh + (size_t)e0.x * 128 + lane * 4);
        uint2 h1 = *(const uint2*)(g_hh + (size_t)e1.x * 128 + lane * 4);
        float2 p0 = __half22float2(u_as_h2(h0.x));
        float2 p1 = __half22float2(u_as_h2(h0.y));
        float2 q0 = __half22float2(u_as_h2(h1.x));
        float2 q1 = __half22float2(u_as_h2(h1.y));
        acc.x  += w0 * p0.x; acc.y  += w0 * p0.y; acc.z  += w0 * p1.x; acc.w  += w0 * p1.y;
        acc2.x += w1 * q0.x; acc2.y += w1 * q0.y; acc2.z += w1 * q1.x; acc2.w += w1 * q1.y;
    }
    if (j < end) {
        uint2 e = g_ew[j];
        float w = __uint_as_float(e.y);
        uint2 h = *(const uint2*)(g_hh + (size_t)e.x * 128 + lane * 4);
        float2 p0 = __half22float2(u_as_h2(h.x));
        float2 p1 = __half22float2(u_as_h2(h.y));
        acc.x += w * p0.x; acc.y += w * p0.y; acc.z += w * p1.x; acc.w += w * p1.y;
    }
    acc.x += acc2.x; acc.y += acc2.y; acc.z += acc2.z; acc.w += acc2.w;
    uint2 o;
    o.x = h2_as_u(__float22half2_rn(make_float2(acc.x, acc.y)));
    o.y = h2_as_u(__float22half2_rn(make_float2(acc.z, acc.w)));
    *(uint2*)(g_ah + (size_t)node * 128 + lane * 4) = o;
}

// ---------------- GEMM (HMMA): g_hh = relu(g_ah @ W + b), [N,128]x[128,128] ----------------
#define PA 72    // A smem pitch (halfs): 144B -> ldmatrix rows hit distinct 16B groups
#define PB 136   // B smem pitch (halfs): 272B -> same

__global__ __launch_bounds__(256, 2) void k_gemm(const float* __restrict__ W,
                                                 const float* __restrict__ bias) {
    __shared__ __align__(16) __half As[128 * PA];  // 18KB
    __shared__ __align__(16) __half Bs[64 * PB];   // 17KB
    int t = threadIdx.x;
    int lane = t & 31, warp = t >> 5;
    int wm = warp & 3, wn = warp >> 2;             // 4 (m) x 2 (n) warps
    int row0 = blockIdx.x * 128;

    float acc[2][8][4];
    #pragma unroll
    for (int mt = 0; mt < 2; mt++)
        #pragma unroll
        for (int nt = 0; nt < 8; nt++)
            #pragma unroll
            for (int d = 0; d < 4; d++) acc[mt][nt][d] = 0.f;

    int lm = lane >> 3, lr = lane & 7;             // ldmatrix addressing helpers

    for (int k0 = 0; k0 < 128; k0 += 64) {
        // A tile: 128 rows x 64 halfs, from g_ah
        #pragma unroll
        for (int i = 0; i < 4; i++) {
            int lin = t + i * 256;                 // 0..1023
            int r = lin >> 3, c8 = (lin & 7) * 8;
            uint4 v = make_uint4(0u, 0u, 0u, 0u);
            if (row0 + r < NN)
                v = *(const uint4*)(g_ah + (size_t)(row0 + r) * 128 + k0 + c8);
            *(uint4*)(As + r * PA + c8) = v;
        }
        // B tile: 64 rows x 128 cols, from fp32 W, convert to fp16
        #pragma unroll
        for (int i = 0; i < 8; i++) {
            int lin = t + i * 256;                 // 0..2047
            int kk = lin >> 5, c4 = (lin & 31) * 4;
            float4 wv = *(const float4*)(W + (size_t)(k0 + kk) * 128 + c4);
            uint2 p;
            p.x = h2_as_u(__float22half2_rn(make_float2(wv.x, wv.y)));
            p.y = h2_as_u(__float22half2_rn(make_float2(wv.z, wv.w)));
            *(uint2*)(Bs + kk * PB + c4) = p;
        }
        __syncthreads();

        #pragma unroll
        for (int kk = 0; kk < 64; kk += 16) {
            unsigned a[2][4];
            #pragma unroll
            for (int mt = 0; mt < 2; mt++) {
                const __half* ap = As + (wm * 32 + mt * 16 + (lm & 1) * 8 + lr) * PA
                                      + kk + (lm >> 1) * 8;
                unsigned addr = (unsigned)__cvta_generic_to_shared(ap);
                asm volatile("ldmatrix.sync.aligned.m8n8.x4.shared.b16 {%0,%1,%2,%3}, [%4];"
                             : "=r"(a[mt][0]), "=r"(a[mt][1]), "=r"(a[mt][2]), "=r"(a[mt][3])
                             : "r"(addr));
            }
            unsigned b[8][2];
            #pragma unroll
            for (int nt16 = 0; nt16 < 4; nt16++) {
                const __half* bp = Bs + (kk + (lm & 1) * 8 + lr) * PB
                                      + wn * 64 + nt16 * 16 + (lm >> 1) * 8;
                unsigned addr = (unsigned)__cvta_generic_to_shared(bp);
                asm volatile("ldmatrix.sync.aligned.m8n8.x4.trans.shared.b16 {%0,%1,%2,%3}, [%4];"
                             : "=r"(b[2*nt16][0]), "=r"(b[2*nt16][1]),
                               "=r"(b[2*nt16+1][0]), "=r"(b[2*nt16+1][1])
                             : "r"(addr));
            }
            #pragma unroll
            for (int mt = 0; mt < 2; mt++)
                #pragma unroll
                for (int nt = 0; nt < 8; nt++) {
                    asm volatile(
                        "mma.sync.aligned.m16n8k16.row.col.f32.f16.f16.f32 "
                        "{%0,%1,%2,%3}, {%4,%5,%6,%7}, {%8,%9}, {%0,%1,%2,%3};"
                        : "+f"(acc[mt][nt][0]), "+f"(acc[mt][nt][1]),
                          "+f"(acc[mt][nt][2]), "+f"(acc[mt][nt][3])
                        : "r"(a[mt][0]), "r"(a[mt][1]), "r"(a[mt][2]), "r"(a[mt][3]),
                          "r"(b[nt][0]), "r"(b[nt][1]));
                }
        }
        __syncthreads();
    }

    // epilogue: bias + relu -> fp16 h
    #pragma unroll
    for (int nt = 0; nt < 8; nt++) {
        int col = wn * 64 + nt * 8 + (lane & 3) * 2;
        float2 bv = *(const float2*)(bias + col);
        #pragma unroll
        for (int mt = 0; mt < 2; mt++) {
            int rA = row0 + wm * 32 + mt * 16 + (lane >> 2);
            if (rA < NN) {
                float2 v = make_float2(fmaxf(acc[mt][nt][0] + bv.x, 0.f),
                                       fmaxf(acc[mt][nt][1] + bv.y, 0.f));
                *(__half2*)(g_hh + (size_t)rA * 128 + col) = __float22half2_rn(v);
            }
            int rB = rA + 8;
            if (rB < NN) {
                float2 v = make_float2(fmaxf(acc[mt][nt][2] + bv.x, 0.f),
                                       fmaxf(acc[mt][nt][3] + bv.y, 0.f));
                *(__half2*)(g_hh + (size_t)rB * 128 + col) = __float22half2_rn(v);
            }
        }
    }
}

// ---------------- mean pool per graph (batch sorted -> binary search bounds) ----------------
__global__ void k_pool(const int* __restrict__ batch) {
    int g = blockIdx.x;   // 0..127
    int c = threadIdx.x;  // 0..127
    int lo = 0, hi = NN;
    while (lo < hi) { int m = (lo + hi) >> 1; if (batch[m] < g) lo = m + 1; else hi = m; }
    int st = lo;
    lo = st; hi = NN;
    while (lo < hi) { int m = (lo + hi) >> 1; if (batch[m] < g + 1) lo = m + 1; else hi = m; }
    int en = lo;
    float s0 = 0.f, s1 = 0.f, s2 = 0.f, s3 = 0.f;
    int n = st;
    for (; n + 3 < en; n += 4) {
        s0 += __half2float(g_hh[(size_t)(n + 0) * 128 + c]);
        s1 += __half2float(g_hh[(size_t)(n + 1) * 128 + c]);
        s2 += __half2float(g_hh[(size_t)(n + 2) * 128 + c]);
        s3 += __half2float(g_hh[(size_t)(n + 3) * 128 + c]);
    }
    for (; n < en; n++) s0 += __half2float(g_hh[(size_t)n * 128 + c]);
    float s = (s0 + s1) + (s2 + s3);
    int cnt = en - st;
    g_pool[g * 128 + c] = s / (float)(cnt > 0 ? cnt : 1);
}

// ---------------- final linear: out = pool @ Wl + bl  [128,5] ----------------
__global__ void k_final(const float* __restrict__ Wl, const float* __restrict__ bl,
                        float* __restrict__ out) {
    int t = blockIdx.x * blockDim.x + threadIdx.x;
    if (t >= NG * NC) return;
    int g = t / NC, c = t % NC;
    float s = bl[c];
    #pragma unroll 8
    for (int k = 0; k < 128; k++) s += g_pool[g * 128 + k] * Wl[k * 5 + c];
    out[t] = s;
}

extern "C" void kernel_launch(void* const* d_in, const int* in_sizes, int n_in,
                              void* d_out, int out_size) {
    const float* x     = (const float*)d_in[0];
    const int*   ei    = (const int*)d_in[1];
    const int*   batch = (const int*)d_in[2];
    const float* W1    = (const float*)d_in[3];
    const float* b1    = (const float*)d_in[4];
    const float* W2    = (const float*)d_in[5];
    const float* b2    = (const float*)d_in[6];
    const float* W3    = (const float*)d_in[7];
    const float* b3    = (const float*)d_in[8];
    const float* Wl    = (const float*)d_in[9];
    const float* bl    = (const float*)d_in[10];
    float* out = (float*)d_out;

    const int* src = ei;          // edge_index[0]
    const int* dst = ei + NE;     // edge_index[1]

    // graph norm + CSR build
    k_init <<<(NN + 255) / 256, 256>>>();
    k_deg  <<<(NE + 255) / 256, 256>>>(dst);
    k_scanA<<<NBLK, 256>>>();
    k_scanB<<<1, 256>>>();
    k_scanC<<<NBLK, 256>>>();
    k_fill <<<(NT + 255) / 256, 256>>>(src, dst);

    // layer 1 (fused propagate-3dim + tiny GEMM + bias + relu)
    k_layer1<<<(NN + 7) / 8, 256>>>(x, W1, b1);

    // layer 2
    k_prop<<<(NN + 7) / 8, 256>>>();
    k_gemm<<<(NN + 127) / 128, 256>>>(W2, b2);

    // layer 3
    k_prop<<<(NN + 7) / 8, 256>>>();
    k_gemm<<<(NN + 127) / 128, 256>>>(W3, b3);

    // pool + classifier head
    k_pool<<<NG, HID>>>(batch);
    k_final<<<(NG * NC + 127) / 128, 128>>>(Wl, bl, out);
}